// round 2
// baseline (speedup 1.0000x reference)
#include <cuda_runtime.h>
#include <math.h>
#include <stdint.h>

#define NN 100000
#define NE 1600000

// ---------------- scratch (device globals; no allocation allowed) ----------------
__device__ float g_y[(size_t)NN * 128];    // dinv-scaled XW
__device__ float g_agg[(size_t)NN * 128];  // aggregation accumulator
__device__ float g_h[(size_t)NN * 128];    // layer activations
__device__ float g_dinv[NN];
__device__ int   g_deg[NN];

// ---------------- small prep kernels ----------------
__global__ void init_deg(int* deg, int n) {
    int i = blockIdx.x * blockDim.x + threadIdx.x;
    if (i < n) deg[i] = 1;  // self-loop
}

// edge_index is int32 (JAX x64 disabled): row 0 = src, row 1 = dst
__global__ void count_deg(const int* __restrict__ dst, int* __restrict__ deg, int E, int N) {
    int e = blockIdx.x * blockDim.x + threadIdx.x;
    if (e >= E) return;
    int d = dst[e];
    if ((unsigned)d < (unsigned)N) atomicAdd(&deg[d], 1);
}

__global__ void calc_dinv(const int* __restrict__ deg, float* __restrict__ dinv, int n) {
    int i = blockIdx.x * blockDim.x + threadIdx.x;
    if (i < n) dinv[i] = rsqrtf((float)deg[i]);
}

// ---------------- GEMM: Y[i,:] = dinv[i] * (X[i,:] @ W); Agg init = Y ----------------
// K = 128 fixed. FO = 128 or 64. Block 256 threads, 8x8 microtile per thread.
template <int FO>
__launch_bounds__(256, 1)
__global__ void gemm_scale(const float* __restrict__ X, const float* __restrict__ W,
                           const float* __restrict__ dinv, float* __restrict__ Y,
                           float* __restrict__ Agg, int N) {
    constexpr int K = 128;
    constexpr int TX = FO / 8;        // threads along cols
    constexpr int TY = 256 / TX;      // threads along rows
    constexpr int BM = TY * 8;        // rows per block (128 or 256)
    constexpr int XST = K + 4;        // padded X row stride in smem

    extern __shared__ float smem[];
    float* Xs = smem;                 // [BM][XST]
    float* Ws = smem + BM * XST;      // [K][FO]

    int tid = threadIdx.x;
    int tx = tid % TX;
    int ty = tid / TX;
    int row0 = blockIdx.x * BM;

    // stage W (row-major [K][FO])
    for (int i = tid; i < K * FO / 4; i += 256)
        ((float4*)Ws)[i] = ((const float4*)W)[i];

    // stage X tile (row-major, padded)
    for (int i = tid; i < BM * (K / 4); i += 256) {
        int r = i >> 5;       // K/4 == 32
        int k4 = i & 31;
        int gr = row0 + r;
        float4 v = (gr < N) ? ((const float4*)X)[(size_t)gr * (K / 4) + k4]
                            : make_float4(0.f, 0.f, 0.f, 0.f);
        *(float4*)&Xs[r * XST + k4 * 4] = v;
    }
    __syncthreads();

    float acc[8][8];
#pragma unroll
    for (int j = 0; j < 8; j++)
#pragma unroll
        for (int c = 0; c < 8; c++) acc[j][c] = 0.f;

#pragma unroll 8
    for (int k = 0; k < K; k++) {
        float b[8];
        *(float4*)&b[0] = *(const float4*)&Ws[k * FO + tx * 8];
        *(float4*)&b[4] = *(const float4*)&Ws[k * FO + tx * 8 + 4];
        float a[8];
#pragma unroll
        for (int j = 0; j < 8; j++) a[j] = Xs[(ty * 8 + j) * XST + k];
#pragma unroll
        for (int j = 0; j < 8; j++)
#pragma unroll
            for (int c = 0; c < 8; c++)
                acc[j][c] = fmaf(a[j], b[c], acc[j][c]);
    }

#pragma unroll
    for (int j = 0; j < 8; j++) {
        int r = row0 + ty * 8 + j;
        if (r < N) {
            float di = dinv[r];
            float4 v0 = make_float4(di * acc[j][0], di * acc[j][1], di * acc[j][2], di * acc[j][3]);
            float4 v1 = make_float4(di * acc[j][4], di * acc[j][5], di * acc[j][6], di * acc[j][7]);
            size_t off = (size_t)r * FO + tx * 8;
            *(float4*)&Y[off] = v0;
            *(float4*)&Y[off + 4] = v1;
            *(float4*)&Agg[off] = v0;    // self-loop contribution
            *(float4*)&Agg[off + 4] = v1;
        }
    }
}

// ---------------- scatter: Agg[dst] += Y[src] ----------------
__device__ __forceinline__ void red_add_v4(float4* p, float4 v) {
    asm volatile("red.global.add.v4.f32 [%0], {%1, %2, %3, %4};"
                 :: "l"(p), "f"(v.x), "f"(v.y), "f"(v.z), "f"(v.w)
                 : "memory");
}

// FO=128: one warp per edge (32 lanes x float4 = 128 floats)
__global__ void scatter128(const int* __restrict__ src, const int* __restrict__ dst,
                           const float4* __restrict__ Y, float4* __restrict__ Agg,
                           int E, int N) {
    int w = (blockIdx.x * blockDim.x + threadIdx.x) >> 5;
    int lane = threadIdx.x & 31;
    if (w >= E) return;
    int s = src[w];
    int d = dst[w];
    if ((unsigned)s >= (unsigned)N || (unsigned)d >= (unsigned)N) return;
    float4 v = Y[(size_t)s * 32 + lane];
    red_add_v4(&Agg[(size_t)d * 32 + lane], v);
}

// FO=64: half-warp per edge (16 lanes x float4 = 64 floats)
__global__ void scatter64(const int* __restrict__ src, const int* __restrict__ dst,
                          const float4* __restrict__ Y, float4* __restrict__ Agg,
                          int E, int N) {
    int w = (blockIdx.x * blockDim.x + threadIdx.x) >> 5;
    int lane = threadIdx.x & 31;
    int sub = lane >> 4;
    int l16 = lane & 15;
    int e = w * 2 + sub;
    if (e >= E) return;
    int s = src[e];
    int d = dst[e];
    if ((unsigned)s >= (unsigned)N || (unsigned)d >= (unsigned)N) return;
    float4 v = Y[(size_t)s * 16 + l16];
    red_add_v4(&Agg[(size_t)d * 16 + l16], v);
}

// ---------------- epilogue: out = relu(dinv * agg + b) ----------------
template <int FO>
__global__ void finish_relu(const float4* __restrict__ Agg, const float* __restrict__ dinv,
                            const float* __restrict__ bias, float4* __restrict__ Out, int N) {
    int i = blockIdx.x * blockDim.x + threadIdx.x;
    constexpr int C4 = FO / 4;
    if (i >= N * C4) return;
    int r = i / C4;
    int c4 = i % C4;
    float di = dinv[r];
    float4 v = Agg[i];
    float4 b = ((const float4*)bias)[c4];
    float4 o;
    o.x = fmaxf(fmaf(di, v.x, b.x), 0.f);
    o.y = fmaxf(fmaf(di, v.y, b.y), 0.f);
    o.z = fmaxf(fmaf(di, v.z, b.z), 0.f);
    o.w = fmaxf(fmaf(di, v.w, b.w), 0.f);
    Out[i] = o;
}

// ---------------- final: out = log_softmax(dinv * agg + b) over 64 ch, warp/node ----------------
__global__ void finish_lsm(const float* __restrict__ Agg, const float* __restrict__ dinv,
                           const float* __restrict__ bias, float* __restrict__ Out, int N) {
    int node = (blockIdx.x * blockDim.x + threadIdx.x) >> 5;
    int lane = threadIdx.x & 31;
    if (node >= N) return;
    float di = dinv[node];
    size_t base = (size_t)node * 64;
    float v0 = fmaf(di, Agg[base + lane], bias[lane]);
    float v1 = fmaf(di, Agg[base + 32 + lane], bias[32 + lane]);
    float m = fmaxf(v0, v1);
#pragma unroll
    for (int o = 16; o > 0; o >>= 1)
        m = fmaxf(m, __shfl_xor_sync(0xFFFFFFFFu, m, o));
    float s = expf(v0 - m) + expf(v1 - m);
#pragma unroll
    for (int o = 16; o > 0; o >>= 1)
        s += __shfl_xor_sync(0xFFFFFFFFu, s, o);
    float ls = m + logf(s);
    Out[base + lane] = v0 - ls;
    Out[base + 32 + lane] = v1 - ls;
}

// ---------------- driver ----------------
extern "C" void kernel_launch(void* const* d_in, const int* in_sizes, int n_in,
                              void* d_out, int out_size) {
    const float* x   = (const float*)d_in[0];
    const int*   ei  = (const int*)d_in[1];   // int32 edge_index [2, E]
    const float* W1  = (const float*)d_in[2];
    const float* b1  = (const float*)d_in[3];
    const float* W2  = (const float*)d_in[4];
    const float* b2  = (const float*)d_in[5];
    const float* W3  = (const float*)d_in[6];
    const float* b3  = (const float*)d_in[7];
    float* out = (float*)d_out;

    int N = in_sizes[0] / 128;
    int E = in_sizes[1] / 2;

    const int* src = ei;        // row 0
    const int* dst = ei + E;    // row 1

    float *y, *agg, *h, *dinv;
    int *deg;
    cudaGetSymbolAddress((void**)&y, g_y);
    cudaGetSymbolAddress((void**)&agg, g_agg);
    cudaGetSymbolAddress((void**)&h, g_h);
    cudaGetSymbolAddress((void**)&dinv, g_dinv);
    cudaGetSymbolAddress((void**)&deg, g_deg);

    constexpr int SMEM128 = (128 * 132 + 128 * 128) * 4;  // 133120 B
    constexpr int SMEM64  = (256 * 132 + 128 * 64) * 4;   // 167936 B
    cudaFuncSetAttribute(gemm_scale<128>, cudaFuncAttributeMaxDynamicSharedMemorySize, SMEM128);
    cudaFuncSetAttribute(gemm_scale<64>,  cudaFuncAttributeMaxDynamicSharedMemorySize, SMEM64);

    int nb_nodes = (N + 255) / 256;
    int nb_edges = (E + 255) / 256;

    // prep: degree + dinv
    init_deg<<<nb_nodes, 256>>>(deg, N);
    count_deg<<<nb_edges, 256>>>(dst, deg, E, N);
    calc_dinv<<<nb_nodes, 256>>>(deg, dinv, N);

    int gemm128_blocks = (N + 127) / 128;
    int gemm64_blocks  = (N + 255) / 256;
    int scat128_blocks = (E + 7) / 8;            // 8 warps/block, 1 edge/warp
    int scat64_blocks  = (E / 2 + 7) / 8;        // 2 edges/warp
    int fin128_blocks  = (N * 32 + 255) / 256;   // N*128/4 float4s
    int lsm_blocks     = (N * 32 + 255) / 256;   // warp per node

    // ---- layer 1: x -> h ----
    gemm_scale<128><<<gemm128_blocks, 256, SMEM128>>>(x, W1, dinv, y, agg, N);
    scatter128<<<scat128_blocks, 256>>>(src, dst, (const float4*)y, (float4*)agg, E, N);
    finish_relu<128><<<fin128_blocks, 256>>>((const float4*)agg, dinv, b1, (float4*)h, N);

    // ---- layer 2: h -> h ----
    gemm_scale<128><<<gemm128_blocks, 256, SMEM128>>>(h, W2, dinv, y, agg, N);
    scatter128<<<scat128_blocks, 256>>>(src, dst, (const float4*)y, (float4*)agg, E, N);
    finish_relu<128><<<fin128_blocks, 256>>>((const float4*)agg, dinv, b2, (float4*)h, N);

    // ---- layer 3: h -> out (64 ch) + log_softmax ----
    gemm_scale<64><<<gemm64_blocks, 256, SMEM64>>>(h, W3, dinv, y, agg, N);
    scatter64<<<scat64_blocks, 256>>>(src, dst, (const float4*)y, (float4*)agg, E, N);
    finish_lsm<<<lsm_blocks, 256>>>(agg, dinv, b3, out, N);
}

// round 3
// speedup vs baseline: 2.0685x; 2.0685x over previous
#include <cuda_runtime.h>
#include <math.h>
#include <stdint.h>

#define NN 100000
#define NE 1600000

// ---------------- scratch (device globals) ----------------
__device__ float g_y[(size_t)NN * 128];    // dinv-scaled XW
__device__ float g_h[(size_t)NN * 128];    // layer activations
__device__ float g_dinv[NN];
__device__ int   g_cnt[NN];                // in-degree (without self)
__device__ int   g_excl[NN];               // block-local exclusive scan
__device__ int   g_bsum[128];              // per-block sums
__device__ int   g_rowptr[NN + 1];
__device__ int   g_cursor[NN];
__device__ int   g_col[NE];                // CSR column (src) indices

// ---------------- prep: degree / dinv ----------------
__global__ void zero_cnt(int* cnt, int n) {
    int i = blockIdx.x * blockDim.x + threadIdx.x;
    if (i < n) cnt[i] = 0;
}

__global__ void count_deg(const int* __restrict__ dst, int* __restrict__ cnt, int E, int N) {
    int e = blockIdx.x * blockDim.x + threadIdx.x;
    if (e >= E) return;
    int d = dst[e];
    if ((unsigned)d < (unsigned)N) atomicAdd(&cnt[d], 1);
}

__global__ void calc_dinv(const int* __restrict__ cnt, float* __restrict__ dinv, int n) {
    int i = blockIdx.x * blockDim.x + threadIdx.x;
    if (i < n) dinv[i] = rsqrtf((float)(cnt[i] + 1));  // +1 self-loop
}

// ---------------- prefix scan (3 kernels) ----------------
__global__ void scan_block(const int* __restrict__ cnt, int* __restrict__ excl,
                           int* __restrict__ bsum, int n) {
    __shared__ int sh[1024];
    int tid = threadIdx.x;
    int i = blockIdx.x * 1024 + tid;
    int v = (i < n) ? cnt[i] : 0;
    sh[tid] = v;
    __syncthreads();
#pragma unroll
    for (int off = 1; off < 1024; off <<= 1) {
        int t = (tid >= off) ? sh[tid - off] : 0;
        __syncthreads();
        sh[tid] += t;
        __syncthreads();
    }
    if (i < n) excl[i] = sh[tid] - v;
    if (tid == 1023) bsum[blockIdx.x] = sh[1023];
}

__global__ void scan_partials(int* bsum, int nb) {
    if (threadIdx.x == 0 && blockIdx.x == 0) {
        int run = 0;
        for (int b = 0; b < nb; b++) { int t = bsum[b]; bsum[b] = run; run += t; }
    }
}

__global__ void scan_finish(const int* __restrict__ excl, const int* __restrict__ bsum,
                            int* __restrict__ rowptr, int* __restrict__ cursor, int n, int E) {
    int i = blockIdx.x * blockDim.x + threadIdx.x;
    if (i < n) {
        int v = excl[i] + bsum[i >> 10];
        rowptr[i] = v;
        cursor[i] = v;
    } else if (i == n) {
        rowptr[n] = E;
    }
}

__global__ void fill_csr(const int* __restrict__ src, const int* __restrict__ dst,
                         int* __restrict__ cursor, int* __restrict__ col, int E, int N) {
    int e = blockIdx.x * blockDim.x + threadIdx.x;
    if (e >= E) return;
    int d = dst[e];
    if ((unsigned)d >= (unsigned)N) return;
    int p = atomicAdd(&cursor[d], 1);
    col[p] = src[e];
}

// ---------------- GEMM: Y[i,:] = dinv[i] * (X[i,:] @ W), K-chunked ----------------
// K = 128 in 2 chunks of 64. FO=128: 256 thr; FO=64: 128 thr. BM=128, 8x8 microtile.
template <int FO>
__launch_bounds__(FO * 2, 1)
__global__ void gemm_scale(const float* __restrict__ X, const float* __restrict__ W,
                           const float* __restrict__ dinv, float* __restrict__ Y, int N) {
    constexpr int K = 128;
    constexpr int KC = 64;            // k-chunk
    constexpr int NT = FO * 2;        // threads (256 or 128)
    constexpr int TX = FO / 8;
    constexpr int TY = NT / TX;       // 16
    constexpr int BM = TY * 8;        // 128
    constexpr int XST = KC + 4;       // padded chunk stride

    extern __shared__ float smem[];
    float* Xs = smem;                 // [BM][XST]
    float* Ws = smem + BM * XST;      // [KC][FO]

    int tid = threadIdx.x;
    int tx = tid % TX;
    int ty = tid / TX;
    int row0 = blockIdx.x * BM;

    float acc[8][8];
#pragma unroll
    for (int j = 0; j < 8; j++)
#pragma unroll
        for (int c = 0; c < 8; c++) acc[j][c] = 0.f;

#pragma unroll
    for (int kc = 0; kc < K / KC; kc++) {
        if (kc > 0) __syncthreads();  // reads of previous chunk done
        // stage W chunk rows [kc*KC, kc*KC+KC) of [K][FO]
        for (int i = tid; i < KC * FO / 4; i += NT)
            ((float4*)Ws)[i] = ((const float4*)W)[kc * (KC * FO / 4) + i];
        // stage X chunk: each row's KC floats = 16 float4
        for (int i = tid; i < BM * (KC / 4); i += NT) {
            int r = i >> 4;
            int k4 = i & 15;
            int gr = row0 + r;
            float4 v = (gr < N) ? ((const float4*)X)[(size_t)gr * (K / 4) + kc * (KC / 4) + k4]
                                : make_float4(0.f, 0.f, 0.f, 0.f);
            *(float4*)&Xs[r * XST + k4 * 4] = v;
        }
        __syncthreads();

#pragma unroll 8
        for (int k = 0; k < KC; k++) {
            float b[8];
            *(float4*)&b[0] = *(const float4*)&Ws[k * FO + tx * 8];
            *(float4*)&b[4] = *(const float4*)&Ws[k * FO + tx * 8 + 4];
            float a[8];
#pragma unroll
            for (int j = 0; j < 8; j++) a[j] = Xs[(ty * 8 + j) * XST + k];
#pragma unroll
            for (int j = 0; j < 8; j++)
#pragma unroll
                for (int c = 0; c < 8; c++)
                    acc[j][c] = fmaf(a[j], b[c], acc[j][c]);
        }
    }

#pragma unroll
    for (int j = 0; j < 8; j++) {
        int r = row0 + ty * 8 + j;
        if (r < N) {
            float di = dinv[r];
            float4 v0 = make_float4(di * acc[j][0], di * acc[j][1], di * acc[j][2], di * acc[j][3]);
            float4 v1 = make_float4(di * acc[j][4], di * acc[j][5], di * acc[j][6], di * acc[j][7]);
            size_t off = (size_t)r * FO + tx * 8;
            *(float4*)&Y[off] = v0;
            *(float4*)&Y[off + 4] = v1;
        }
    }
}

// ---------------- fused pull-aggregation + relu: warp per node, 128 ch ----------------
__global__ void agg_relu128(const int* __restrict__ rowptr, const int* __restrict__ col,
                            const float4* __restrict__ Y, const float* __restrict__ dinv,
                            const float* __restrict__ bias, float4* __restrict__ H, int N) {
    int node = (blockIdx.x * blockDim.x + threadIdx.x) >> 5;
    int lane = threadIdx.x & 31;
    if (node >= N) return;
    float4 acc = Y[(size_t)node * 32 + lane];   // self-loop
    int j = rowptr[node];
    int end = rowptr[node + 1];
    for (; j + 4 <= end; j += 4) {
        int s0 = __ldg(&col[j]);
        int s1 = __ldg(&col[j + 1]);
        int s2 = __ldg(&col[j + 2]);
        int s3 = __ldg(&col[j + 3]);
        float4 v0 = Y[(size_t)s0 * 32 + lane];
        float4 v1 = Y[(size_t)s1 * 32 + lane];
        float4 v2 = Y[(size_t)s2 * 32 + lane];
        float4 v3 = Y[(size_t)s3 * 32 + lane];
        acc.x += v0.x + v1.x + v2.x + v3.x;
        acc.y += v0.y + v1.y + v2.y + v3.y;
        acc.z += v0.z + v1.z + v2.z + v3.z;
        acc.w += v0.w + v1.w + v2.w + v3.w;
    }
    for (; j < end; j++) {
        int s = __ldg(&col[j]);
        float4 v = Y[(size_t)s * 32 + lane];
        acc.x += v.x; acc.y += v.y; acc.z += v.z; acc.w += v.w;
    }
    float di = dinv[node];
    float4 b = ((const float4*)bias)[lane];
    float4 o;
    o.x = fmaxf(fmaf(di, acc.x, b.x), 0.f);
    o.y = fmaxf(fmaf(di, acc.y, b.y), 0.f);
    o.z = fmaxf(fmaf(di, acc.z, b.z), 0.f);
    o.w = fmaxf(fmaf(di, acc.w, b.w), 0.f);
    H[(size_t)node * 32 + lane] = o;
}

// ---------------- fused pull-aggregation + log_softmax: warp per node, 64 ch ----------------
__global__ void agg_lsm64(const int* __restrict__ rowptr, const int* __restrict__ col,
                          const float2* __restrict__ Y, const float* __restrict__ dinv,
                          const float* __restrict__ bias, float2* __restrict__ Out, int N) {
    int node = (blockIdx.x * blockDim.x + threadIdx.x) >> 5;
    int lane = threadIdx.x & 31;
    if (node >= N) return;
    float2 acc = Y[(size_t)node * 32 + lane];
    int j = rowptr[node];
    int end = rowptr[node + 1];
    for (; j + 4 <= end; j += 4) {
        int s0 = __ldg(&col[j]);
        int s1 = __ldg(&col[j + 1]);
        int s2 = __ldg(&col[j + 2]);
        int s3 = __ldg(&col[j + 3]);
        float2 v0 = Y[(size_t)s0 * 32 + lane];
        float2 v1 = Y[(size_t)s1 * 32 + lane];
        float2 v2 = Y[(size_t)s2 * 32 + lane];
        float2 v3 = Y[(size_t)s3 * 32 + lane];
        acc.x += v0.x + v1.x + v2.x + v3.x;
        acc.y += v0.y + v1.y + v2.y + v3.y;
    }
    for (; j < end; j++) {
        int s = __ldg(&col[j]);
        float2 v = Y[(size_t)s * 32 + lane];
        acc.x += v.x; acc.y += v.y;
    }
    float di = dinv[node];
    float2 b = ((const float2*)bias)[lane];
    float vx = fmaf(di, acc.x, b.x);
    float vy = fmaf(di, acc.y, b.y);
    float m = fmaxf(vx, vy);
#pragma unroll
    for (int o = 16; o > 0; o >>= 1)
        m = fmaxf(m, __shfl_xor_sync(0xFFFFFFFFu, m, o));
    float s = expf(vx - m) + expf(vy - m);
#pragma unroll
    for (int o = 16; o > 0; o >>= 1)
        s += __shfl_xor_sync(0xFFFFFFFFu, s, o);
    float ls = m + logf(s);
    float2 o2;
    o2.x = vx - ls;
    o2.y = vy - ls;
    Out[(size_t)node * 32 + lane] = o2;
}

// ---------------- driver ----------------
extern "C" void kernel_launch(void* const* d_in, const int* in_sizes, int n_in,
                              void* d_out, int out_size) {
    const float* x   = (const float*)d_in[0];
    const int*   ei  = (const int*)d_in[1];   // int32 edge_index [2, E]
    const float* W1  = (const float*)d_in[2];
    const float* b1  = (const float*)d_in[3];
    const float* W2  = (const float*)d_in[4];
    const float* b2  = (const float*)d_in[5];
    const float* W3  = (const float*)d_in[6];
    const float* b3  = (const float*)d_in[7];
    float* out = (float*)d_out;

    int N = in_sizes[0] / 128;
    int E = in_sizes[1] / 2;
    const int* src = ei;
    const int* dst = ei + E;

    float *y, *h, *dinv;
    int *cnt, *excl, *bsum, *rowptr, *cursor, *col;
    cudaGetSymbolAddress((void**)&y, g_y);
    cudaGetSymbolAddress((void**)&h, g_h);
    cudaGetSymbolAddress((void**)&dinv, g_dinv);
    cudaGetSymbolAddress((void**)&cnt, g_cnt);
    cudaGetSymbolAddress((void**)&excl, g_excl);
    cudaGetSymbolAddress((void**)&bsum, g_bsum);
    cudaGetSymbolAddress((void**)&rowptr, g_rowptr);
    cudaGetSymbolAddress((void**)&cursor, g_cursor);
    cudaGetSymbolAddress((void**)&col, g_col);

    constexpr int SMEM128 = (128 * 68 + 64 * 128) * 4;  // 67584 B
    constexpr int SMEM64  = (128 * 68 + 64 * 64) * 4;   // 51200 B
    cudaFuncSetAttribute(gemm_scale<128>, cudaFuncAttributeMaxDynamicSharedMemorySize, SMEM128);
    cudaFuncSetAttribute(gemm_scale<64>,  cudaFuncAttributeMaxDynamicSharedMemorySize, SMEM64);

    int nb_nodes = (N + 255) / 256;
    int nb_edges = (E + 255) / 256;
    int nb_scan  = (N + 1023) / 1024;

    // ---- prep: degree, dinv, CSR ----
    zero_cnt<<<nb_nodes, 256>>>(cnt, N);
    count_deg<<<nb_edges, 256>>>(dst, cnt, E, N);
    calc_dinv<<<nb_nodes, 256>>>(cnt, dinv, N);
    scan_block<<<nb_scan, 1024>>>(cnt, excl, bsum, N);
    scan_partials<<<1, 32>>>(bsum, nb_scan);
    scan_finish<<<(N + 256) / 256, 256>>>(excl, bsum, rowptr, cursor, N, E);
    fill_csr<<<nb_edges, 256>>>(src, dst, cursor, col, E, N);

    int gemm_blocks = (N + 127) / 128;
    int agg_blocks  = ((size_t)N * 32 + 255) / 256;

    // ---- layer 1 ----
    gemm_scale<128><<<gemm_blocks, 256, SMEM128>>>(x, W1, dinv, y, N);
    agg_relu128<<<agg_blocks, 256>>>(rowptr, col, (const float4*)y, dinv, b1, (float4*)h, N);
    // ---- layer 2 ----
    gemm_scale<128><<<gemm_blocks, 256, SMEM128>>>(h, W2, dinv, y, N);
    agg_relu128<<<agg_blocks, 256>>>(rowptr, col, (const float4*)y, dinv, b2, (float4*)h, N);
    // ---- layer 3 ----
    gemm_scale<64><<<gemm_blocks, 128, SMEM64>>>(h, W3, dinv, y, N);
    agg_lsm64<<<agg_blocks, 256>>>(rowptr, col, (const float2*)y, dinv, b3, (float2*)out, N);
}

// round 4
// speedup vs baseline: 2.2783x; 1.1014x over previous
#include <cuda_runtime.h>
#include <cuda_fp16.h>
#include <math.h>
#include <stdint.h>

#define NN 100000
#define NE 1600000

// ---------------- scratch (device globals) ----------------
__device__ __half g_yh[(size_t)NN * 128];  // dinv-scaled XW, fp16
__device__ float  g_h[(size_t)NN * 128];   // layer activations fp32
__device__ float  g_dinv[NN];
__device__ int    g_cnt[NN];
__device__ int    g_excl[NN];
__device__ int    g_bsum[128];
__device__ int    g_rowptr[NN + 1];
__device__ int    g_cursor[NN];
__device__ int    g_col[NE];

// ---------------- packed f32x2 helpers ----------------
#define FMA_F32X2(d, a, b, c) \
    asm("fma.rn.f32x2 %0, %1, %2, %3;" : "=l"(d) : "l"(a), "l"(b), "l"(c))
#define UNPACK_F32X2(lo, hi, v) \
    asm("mov.b64 {%0, %1}, %2;" : "=r"(lo), "=r"(hi) : "l"(v))

// ---------------- prep: degree / dinv ----------------
__global__ void zero_cnt(int* cnt, int n) {
    int i = blockIdx.x * blockDim.x + threadIdx.x;
    if (i < n) cnt[i] = 0;
}

__global__ void count_deg(const int* __restrict__ dst, int* __restrict__ cnt, int E, int N) {
    int e = blockIdx.x * blockDim.x + threadIdx.x;
    if (e >= E) return;
    int d = dst[e];
    if ((unsigned)d < (unsigned)N) atomicAdd(&cnt[d], 1);
}

__global__ void calc_dinv(const int* __restrict__ cnt, float* __restrict__ dinv, int n) {
    int i = blockIdx.x * blockDim.x + threadIdx.x;
    if (i < n) dinv[i] = rsqrtf((float)(cnt[i] + 1));
}

// ---------------- prefix scan ----------------
__global__ void scan_block(const int* __restrict__ cnt, int* __restrict__ excl,
                           int* __restrict__ bsum, int n) {
    __shared__ int sh[1024];
    int tid = threadIdx.x;
    int i = blockIdx.x * 1024 + tid;
    int v = (i < n) ? cnt[i] : 0;
    sh[tid] = v;
    __syncthreads();
#pragma unroll
    for (int off = 1; off < 1024; off <<= 1) {
        int t = (tid >= off) ? sh[tid - off] : 0;
        __syncthreads();
        sh[tid] += t;
        __syncthreads();
    }
    if (i < n) excl[i] = sh[tid] - v;
    if (tid == 1023) bsum[blockIdx.x] = sh[1023];
}

// parallel exclusive scan of block sums (nb <= 128), one block
__global__ void scan_partials(int* bsum, int nb) {
    __shared__ int sh[128];
    int tid = threadIdx.x;
    int v = (tid < nb) ? bsum[tid] : 0;
    sh[tid] = v;
    __syncthreads();
#pragma unroll
    for (int off = 1; off < 128; off <<= 1) {
        int t = (tid >= off) ? sh[tid - off] : 0;
        __syncthreads();
        sh[tid] += t;
        __syncthreads();
    }
    if (tid < nb) bsum[tid] = sh[tid] - v;
}

__global__ void scan_finish(const int* __restrict__ excl, const int* __restrict__ bsum,
                            int* __restrict__ rowptr, int* __restrict__ cursor, int n, int E) {
    int i = blockIdx.x * blockDim.x + threadIdx.x;
    if (i < n) {
        int v = excl[i] + bsum[i >> 10];
        rowptr[i] = v;
        cursor[i] = v;
    } else if (i == n) {
        rowptr[n] = E;
    }
}

__global__ void fill_csr(const int* __restrict__ src, const int* __restrict__ dst,
                         int* __restrict__ cursor, int* __restrict__ col, int E, int N) {
    int e = blockIdx.x * blockDim.x + threadIdx.x;
    if (e >= E) return;
    int d = dst[e];
    if ((unsigned)d >= (unsigned)N) return;
    int p = atomicAdd(&cursor[d], 1);
    col[p] = src[e];
}

// ---------------- GEMM with packed f32x2 FMAs ----------------
// Yh[i,:] = half(dinv[i] * (X[i,:] @ W)). K=128 in 2 chunks of 64.
// BM=128 rows/block, 8x8 microtile, row-paired accumulators (4x8 f32x2).
// X tile stored transposed in smem -> A-pairs are direct LDS.64.
// W chunk stored duplicated ((w,w) float2) in a chunked layout -> B-pairs are
// conflict-free LDS.128, zero per-k packing instructions.
template <int FO>
__launch_bounds__(FO * 2, FO == 128 ? 2 : 3)
__global__ void gemm_f32x2(const float* __restrict__ X, const float* __restrict__ W,
                           const float* __restrict__ dinv, __half* __restrict__ Yh, int N) {
    constexpr int K = 128;
    constexpr int KC = 64;
    constexpr int NT = FO * 2;       // 256 or 128 threads
    constexpr int TX = FO / 8;       // 16 or 8
    constexpr int TY = NT / TX;      // 16
    constexpr int BM = TY * 8;       // 128
    constexpr int SLOTS = FO / 2;    // ulonglong2 slots per k row of Ws2

    extern __shared__ float smem[];
    float* XsT = smem;                         // [KC][BM] transposed
    float* Ws2f = smem + KC * BM;              // [KC][SLOTS] ulonglong2 slots

    int tid = threadIdx.x;
    int tx = tid % TX;
    int ty = tid / TX;
    int row0 = blockIdx.x * BM;

    unsigned long long acc2[4][8];
#pragma unroll
    for (int p = 0; p < 4; p++)
#pragma unroll
        for (int c = 0; c < 8; c++) acc2[p][c] = 0ULL;

#pragma unroll
    for (int kc = 0; kc < K / KC; kc++) {
        if (kc > 0) __syncthreads();

        // stage X chunk transposed: XsT[k][r]
        for (int i = tid; i < BM * (KC / 4); i += NT) {
            int r = i % BM;
            int kq = i / BM;   // 0..15
            int gr = row0 + r;
            float4 v = (gr < N) ? ((const float4*)X)[(size_t)gr * (K / 4) + kc * (KC / 4) + kq]
                                : make_float4(0.f, 0.f, 0.f, 0.f);
            XsT[(kq * 4 + 0) * BM + r] = v.x;
            XsT[(kq * 4 + 1) * BM + r] = v.y;
            XsT[(kq * 4 + 2) * BM + r] = v.z;
            XsT[(kq * 4 + 3) * BM + r] = v.w;
        }
        // stage W chunk duplicated: slot s = k*SLOTS + q*TX + tx holds cols
        // (tx*8 + 2q, tx*8 + 2q + 1), each as (w,w) float2.
        for (int s = tid; s < KC * SLOTS; s += NT) {
            int k = s / SLOTS;
            int p16 = s % SLOTS;
            int stx = p16 % TX;
            int q = p16 / TX;
            int c0 = stx * 8 + q * 2;
            float w0 = W[(size_t)(kc * KC + k) * FO + c0];
            float w1 = W[(size_t)(kc * KC + k) * FO + c0 + 1];
            ((float2*)Ws2f)[s * 2 + 0] = make_float2(w0, w0);
            ((float2*)Ws2f)[s * 2 + 1] = make_float2(w1, w1);
        }
        __syncthreads();

#pragma unroll 8
        for (int k = 0; k < KC; k++) {
            unsigned long long a2[4];
#pragma unroll
            for (int p = 0; p < 4; p++)
                a2[p] = *(const unsigned long long*)&XsT[k * BM + ty * 8 + 2 * p];
            unsigned long long b2[8];
#pragma unroll
            for (int q = 0; q < 4; q++) {
                ulonglong2 t = *(const ulonglong2*)&Ws2f[(k * SLOTS + q * TX + tx) * 4];
                b2[2 * q] = t.x;
                b2[2 * q + 1] = t.y;
            }
#pragma unroll
            for (int p = 0; p < 4; p++)
#pragma unroll
                for (int c = 0; c < 8; c++)
                    FMA_F32X2(acc2[p][c], a2[p], b2[c], acc2[p][c]);
        }
    }

    // epilogue: unpack row pairs, scale by dinv, convert to half, 16B stores
#pragma unroll
    for (int p = 0; p < 4; p++) {
        unsigned lo[8], hi[8];
#pragma unroll
        for (int c = 0; c < 8; c++) UNPACK_F32X2(lo[c], hi[c], acc2[p][c]);
        int r0 = row0 + ty * 8 + 2 * p;
#pragma unroll
        for (int half_sel = 0; half_sel < 2; half_sel++) {
            int r = r0 + half_sel;
            if (r < N) {
                float di = dinv[r];
                unsigned* v = half_sel ? hi : lo;
                __half2 h0 = __floats2half2_rn(di * __uint_as_float(v[0]), di * __uint_as_float(v[1]));
                __half2 h1 = __floats2half2_rn(di * __uint_as_float(v[2]), di * __uint_as_float(v[3]));
                __half2 h2 = __floats2half2_rn(di * __uint_as_float(v[4]), di * __uint_as_float(v[5]));
                __half2 h3 = __floats2half2_rn(di * __uint_as_float(v[6]), di * __uint_as_float(v[7]));
                uint4 u;
                u.x = *(unsigned*)&h0;
                u.y = *(unsigned*)&h1;
                u.z = *(unsigned*)&h2;
                u.w = *(unsigned*)&h3;
                *(uint4*)&Yh[(size_t)r * FO + tx * 8] = u;
            }
        }
    }
}

// ---------------- half -> float helpers ----------------
__device__ __forceinline__ float4 h4_to_f4(uint2 u) {
    __half2 a = *(__half2*)&u.x;
    __half2 b = *(__half2*)&u.y;
    float2 fa = __half22float2(a);
    float2 fb = __half22float2(b);
    return make_float4(fa.x, fa.y, fb.x, fb.y);
}

// ---------------- fused pull-aggregation + relu: warp per node, 128 ch ----------------
__global__ void agg_relu128(const int* __restrict__ rowptr, const int* __restrict__ col,
                            const __half* __restrict__ Yh, const float* __restrict__ dinv,
                            const float* __restrict__ bias, float4* __restrict__ H, int N) {
    int node = (blockIdx.x * blockDim.x + threadIdx.x) >> 5;
    int lane = threadIdx.x & 31;
    if (node >= N) return;
    const uint2* Y2 = (const uint2*)Yh;   // 4 half per uint2; 32 lanes * 4 = 128 ch
    float4 acc = h4_to_f4(Y2[(size_t)node * 32 + lane]);   // self
    int j = rowptr[node];
    int end = rowptr[node + 1];
    for (; j + 4 <= end; j += 4) {
        int s0 = __ldg(&col[j]);
        int s1 = __ldg(&col[j + 1]);
        int s2 = __ldg(&col[j + 2]);
        int s3 = __ldg(&col[j + 3]);
        float4 v0 = h4_to_f4(Y2[(size_t)s0 * 32 + lane]);
        float4 v1 = h4_to_f4(Y2[(size_t)s1 * 32 + lane]);
        float4 v2 = h4_to_f4(Y2[(size_t)s2 * 32 + lane]);
        float4 v3 = h4_to_f4(Y2[(size_t)s3 * 32 + lane]);
        acc.x += v0.x + v1.x + v2.x + v3.x;
        acc.y += v0.y + v1.y + v2.y + v3.y;
        acc.z += v0.z + v1.z + v2.z + v3.z;
        acc.w += v0.w + v1.w + v2.w + v3.w;
    }
    for (; j < end; j++) {
        int s = __ldg(&col[j]);
        float4 v = h4_to_f4(Y2[(size_t)s * 32 + lane]);
        acc.x += v.x; acc.y += v.y; acc.z += v.z; acc.w += v.w;
    }
    float di = dinv[node];
    float4 b = ((const float4*)bias)[lane];
    float4 o;
    o.x = fmaxf(fmaf(di, acc.x, b.x), 0.f);
    o.y = fmaxf(fmaf(di, acc.y, b.y), 0.f);
    o.z = fmaxf(fmaf(di, acc.z, b.z), 0.f);
    o.w = fmaxf(fmaf(di, acc.w, b.w), 0.f);
    H[(size_t)node * 32 + lane] = o;
}

// ---------------- fused pull-aggregation + log_softmax: warp per node, 64 ch ----------------
__global__ void agg_lsm64(const int* __restrict__ rowptr, const int* __restrict__ col,
                          const __half* __restrict__ Yh, const float* __restrict__ dinv,
                          const float* __restrict__ bias, float2* __restrict__ Out, int N) {
    int node = (blockIdx.x * blockDim.x + threadIdx.x) >> 5;
    int lane = threadIdx.x & 31;
    if (node >= N) return;
    const unsigned* Y1 = (const unsigned*)Yh;  // 2 half per uint; 32 lanes * 2 = 64 ch
    float2 acc;
    {
        __half2 h = *(__half2*)&Y1[(size_t)node * 32 + lane];
        acc = __half22float2(h);
    }
    int j = rowptr[node];
    int end = rowptr[node + 1];
    for (; j + 4 <= end; j += 4) {
        int s0 = __ldg(&col[j]);
        int s1 = __ldg(&col[j + 1]);
        int s2 = __ldg(&col[j + 2]);
        int s3 = __ldg(&col[j + 3]);
        unsigned u0 = Y1[(size_t)s0 * 32 + lane];
        unsigned u1 = Y1[(size_t)s1 * 32 + lane];
        unsigned u2 = Y1[(size_t)s2 * 32 + lane];
        unsigned u3 = Y1[(size_t)s3 * 32 + lane];
        float2 v0 = __half22float2(*(__half2*)&u0);
        float2 v1 = __half22float2(*(__half2*)&u1);
        float2 v2 = __half22float2(*(__half2*)&u2);
        float2 v3 = __half22float2(*(__half2*)&u3);
        acc.x += v0.x + v1.x + v2.x + v3.x;
        acc.y += v0.y + v1.y + v2.y + v3.y;
    }
    for (; j < end; j++) {
        int s = __ldg(&col[j]);
        unsigned u = Y1[(size_t)s * 32 + lane];
        float2 v = __half22float2(*(__half2*)&u);
        acc.x += v.x; acc.y += v.y;
    }
    float di = dinv[node];
    float2 b = ((const float2*)bias)[lane];
    float vx = fmaf(di, acc.x, b.x);
    float vy = fmaf(di, acc.y, b.y);
    float m = fmaxf(vx, vy);
#pragma unroll
    for (int o = 16; o > 0; o >>= 1)
        m = fmaxf(m, __shfl_xor_sync(0xFFFFFFFFu, m, o));
    float s = expf(vx - m) + expf(vy - m);
#pragma unroll
    for (int o = 16; o > 0; o >>= 1)
        s += __shfl_xor_sync(0xFFFFFFFFu, s, o);
    float ls = m + logf(s);
    float2 o2;
    o2.x = vx - ls;
    o2.y = vy - ls;
    Out[(size_t)node * 32 + lane] = o2;
}

// ---------------- driver ----------------
extern "C" void kernel_launch(void* const* d_in, const int* in_sizes, int n_in,
                              void* d_out, int out_size) {
    const float* x   = (const float*)d_in[0];
    const int*   ei  = (const int*)d_in[1];
    const float* W1  = (const float*)d_in[2];
    const float* b1  = (const float*)d_in[3];
    const float* W2  = (const float*)d_in[4];
    const float* b2  = (const float*)d_in[5];
    const float* W3  = (const float*)d_in[6];
    const float* b3  = (const float*)d_in[7];
    float* out = (float*)d_out;

    int N = in_sizes[0] / 128;
    int E = in_sizes[1] / 2;
    const int* src = ei;
    const int* dst = ei + E;

    __half* yh;
    float *h, *dinv;
    int *cnt, *excl, *bsum, *rowptr, *cursor, *col;
    cudaGetSymbolAddress((void**)&yh, g_yh);
    cudaGetSymbolAddress((void**)&h, g_h);
    cudaGetSymbolAddress((void**)&dinv, g_dinv);
    cudaGetSymbolAddress((void**)&cnt, g_cnt);
    cudaGetSymbolAddress((void**)&excl, g_excl);
    cudaGetSymbolAddress((void**)&bsum, g_bsum);
    cudaGetSymbolAddress((void**)&rowptr, g_rowptr);
    cudaGetSymbolAddress((void**)&cursor, g_cursor);
    cudaGetSymbolAddress((void**)&col, g_col);

    // smem: XsT = 64*128*4 = 32768; Ws2 = 64*(FO/2)*16
    constexpr int SMEM128 = 32768 + 64 * 64 * 16;  // 98304
    constexpr int SMEM64  = 32768 + 64 * 32 * 16;  // 65536
    cudaFuncSetAttribute(gemm_f32x2<128>, cudaFuncAttributeMaxDynamicSharedMemorySize, SMEM128);
    cudaFuncSetAttribute(gemm_f32x2<64>,  cudaFuncAttributeMaxDynamicSharedMemorySize, SMEM64);

    int nb_nodes = (N + 255) / 256;
    int nb_edges = (E + 255) / 256;
    int nb_scan  = (N + 1023) / 1024;

    // ---- prep: degree, dinv, CSR ----
    zero_cnt<<<nb_nodes, 256>>>(cnt, N);
    count_deg<<<nb_edges, 256>>>(dst, cnt, E, N);
    calc_dinv<<<nb_nodes, 256>>>(cnt, dinv, N);
    scan_block<<<nb_scan, 1024>>>(cnt, excl, bsum, N);
    scan_partials<<<1, 128>>>(bsum, nb_scan);
    scan_finish<<<(N + 256) / 256, 256>>>(excl, bsum, rowptr, cursor, N, E);
    fill_csr<<<nb_edges, 256>>>(src, dst, cursor, col, E, N);

    int gemm_blocks = (N + 127) / 128;
    int agg_blocks  = ((size_t)N * 32 + 255) / 256;

    // ---- layer 1 ----
    gemm_f32x2<128><<<gemm_blocks, 256, SMEM128>>>(x, W1, dinv, yh, N);
    agg_relu128<<<agg_blocks, 256>>>(rowptr, col, yh, dinv, b1, (float4*)h, N);
    // ---- layer 2 ----
    gemm_f32x2<128><<<gemm_blocks, 256, SMEM128>>>(h, W2, dinv, yh, N);
    agg_relu128<<<agg_blocks, 256>>>(rowptr, col, yh, dinv, b2, (float4*)h, N);
    // ---- layer 3 ----
    gemm_f32x2<64><<<gemm_blocks, 128, SMEM64>>>(h, W3, dinv, yh, N);
    agg_lsm64<<<agg_blocks, 256>>>(rowptr, col, yh, dinv, b3, (float2*)out, N);
}

// round 5
// speedup vs baseline: 3.5541x; 1.5600x over previous
#include <cuda_runtime.h>
#include <cuda_fp16.h>
#include <math.h>
#include <stdint.h>

#define NN 100000
#define NE 1600000

// ---------------- scratch (device globals) ----------------
__device__ __half g_xh[(size_t)NN * 128];  // fp16 copy of input x
__device__ __half g_yh[(size_t)NN * 128];  // dinv-scaled XW, fp16
__device__ __half g_h[(size_t)NN * 128];   // layer activations fp16
__device__ float  g_dinv[NN];
__device__ int    g_cnt[NN];
__device__ int    g_excl[NN];
__device__ int    g_bsum[128];
__device__ int    g_rowptr[NN + 1];
__device__ int    g_cursor[NN];
__device__ int    g_col[NE];

// ---------------- prep: degree / dinv ----------------
__global__ void zero_cnt(int* cnt, int n) {
    int i = blockIdx.x * blockDim.x + threadIdx.x;
    if (i < n) cnt[i] = 0;
}

__global__ void count_deg(const int* __restrict__ dst, int* __restrict__ cnt, int E, int N) {
    int e = blockIdx.x * blockDim.x + threadIdx.x;
    if (e >= E) return;
    int d = dst[e];
    if ((unsigned)d < (unsigned)N) atomicAdd(&cnt[d], 1);
}

__global__ void calc_dinv(const int* __restrict__ cnt, float* __restrict__ dinv, int n) {
    int i = blockIdx.x * blockDim.x + threadIdx.x;
    if (i < n) dinv[i] = rsqrtf((float)(cnt[i] + 1));
}

// ---------------- prefix scan ----------------
__global__ void scan_block(const int* __restrict__ cnt, int* __restrict__ excl,
                           int* __restrict__ bsum, int n) {
    __shared__ int sh[1024];
    int tid = threadIdx.x;
    int i = blockIdx.x * 1024 + tid;
    int v = (i < n) ? cnt[i] : 0;
    sh[tid] = v;
    __syncthreads();
#pragma unroll
    for (int off = 1; off < 1024; off <<= 1) {
        int t = (tid >= off) ? sh[tid - off] : 0;
        __syncthreads();
        sh[tid] += t;
        __syncthreads();
    }
    if (i < n) excl[i] = sh[tid] - v;
    if (tid == 1023) bsum[blockIdx.x] = sh[1023];
}

__global__ void scan_partials(int* bsum, int nb) {
    __shared__ int sh[128];
    int tid = threadIdx.x;
    int v = (tid < nb) ? bsum[tid] : 0;
    sh[tid] = v;
    __syncthreads();
#pragma unroll
    for (int off = 1; off < 128; off <<= 1) {
        int t = (tid >= off) ? sh[tid - off] : 0;
        __syncthreads();
        sh[tid] += t;
        __syncthreads();
    }
    if (tid < nb) bsum[tid] = sh[tid] - v;
}

__global__ void scan_finish(const int* __restrict__ excl, const int* __restrict__ bsum,
                            int* __restrict__ rowptr, int* __restrict__ cursor, int n, int E) {
    int i = blockIdx.x * blockDim.x + threadIdx.x;
    if (i < n) {
        int v = excl[i] + bsum[i >> 10];
        rowptr[i] = v;
        cursor[i] = v;
    } else if (i == n) {
        rowptr[n] = E;
    }
}

__global__ void fill_csr(const int* __restrict__ src, const int* __restrict__ dst,
                         int* __restrict__ cursor, int* __restrict__ col, int E, int N) {
    int e = blockIdx.x * blockDim.x + threadIdx.x;
    if (e >= E) return;
    int d = dst[e];
    if ((unsigned)d >= (unsigned)N) return;
    int p = atomicAdd(&cursor[d], 1);
    col[p] = src[e];
}

// ---------------- convert input x to fp16 ----------------
__global__ void conv_x(const float4* __restrict__ X, uint2* __restrict__ Xh, int n4) {
    int i = blockIdx.x * blockDim.x + threadIdx.x;
    if (i >= n4) return;
    float4 v = X[i];
    __half2 a = __floats2half2_rn(v.x, v.y);
    __half2 b = __floats2half2_rn(v.z, v.w);
    uint2 u;
    u.x = *(unsigned*)&a;
    u.y = *(unsigned*)&b;
    Xh[i] = u;
}

// ---------------- HMMA GEMM: Yh = half(dinv * (Xh @ W)) ----------------
// K=128 resident in smem. BM=128 rows/CTA, 8 warps as 4(M) x 2(N).
// A via ldmatrix.x4, B via ldmatrix.x4.trans, mma.m16n8k16.f32.f16.
// smem XOR swizzle: 16B chunk index ^= (row & 7) -> conflict-free LDSM.
#define LDSM_X4(r0, r1, r2, r3, addr) \
    asm volatile("ldmatrix.sync.aligned.m8n8.x4.shared.b16 {%0,%1,%2,%3}, [%4];" \
                 : "=r"(r0), "=r"(r1), "=r"(r2), "=r"(r3) : "r"(addr))
#define LDSM_X4_T(r0, r1, r2, r3, addr) \
    asm volatile("ldmatrix.sync.aligned.m8n8.x4.trans.shared.b16 {%0,%1,%2,%3}, [%4];" \
                 : "=r"(r0), "=r"(r1), "=r"(r2), "=r"(r3) : "r"(addr))
#define MMA_16816(d, a, b) \
    asm volatile("mma.sync.aligned.m16n8k16.row.col.f32.f16.f16.f32 " \
                 "{%0,%1,%2,%3}, {%4,%5,%6,%7}, {%8,%9}, {%0,%1,%2,%3};" \
                 : "+f"(d[0]), "+f"(d[1]), "+f"(d[2]), "+f"(d[3]) \
                 : "r"(a[0]), "r"(a[1]), "r"(a[2]), "r"(a[3]), "r"(b[0]), "r"(b[1]))

template <int FO>
__launch_bounds__(256, 2)
__global__ void gemm_hmma(const __half* __restrict__ Xh, const float* __restrict__ W,
                          const float* __restrict__ dinv, __half* __restrict__ Yh, int N) {
    constexpr int K = 128;
    constexpr int BM = 128;
    constexpr int WN = FO / 2;        // warp cols (64 or 32)
    constexpr int NFRAG = WN / 8;     // n8 fragments per warp (8 or 4)
    constexpr int XROWB = K * 2;      // 256 B
    constexpr int WROWB = FO * 2;     // 256 or 128 B

    extern __shared__ char sm[];
    char* Xs = sm;                    // [BM][K] fp16, swizzled
    char* Ws = sm + BM * XROWB;       // [K][FO] fp16, swizzled

    int tid = threadIdx.x;
    int warp = tid >> 5;
    int l = tid & 31;
    int warp_m = warp & 3;
    int warp_n = warp >> 2;
    int row0 = blockIdx.x * BM;

    // ---- stage X tile: 16B chunks, swizzled ----
    {
        constexpr int CHUNKS = BM * K * 2 / 16;     // 2048
        for (int i = tid; i < CHUNKS; i += 256) {
            int r = i >> 4;          // 16 chunks per row
            int q = i & 15;
            int gr = row0 + r;
            uint4 v = make_uint4(0, 0, 0, 0);
            if (gr < N) v = *(const uint4*)&Xh[(size_t)gr * K + q * 8];
            *(uint4*)&Xs[r * XROWB + ((q ^ (r & 7)) << 4)] = v;
        }
    }
    // ---- stage W (fp32 -> fp16), swizzled ----
    {
        for (int i = tid; i < K * FO / 4; i += 256) {
            int k = i / (FO / 4);
            int c4 = i % (FO / 4);
            float4 v = ((const float4*)W)[(size_t)k * (FO / 4) + c4];
            __half2 h0 = __floats2half2_rn(v.x, v.y);
            __half2 h1 = __floats2half2_rn(v.z, v.w);
            uint2 u;
            u.x = *(unsigned*)&h0;
            u.y = *(unsigned*)&h1;
            int chunk = c4 >> 1;
            *(uint2*)&Ws[k * WROWB + (((chunk ^ (k & 7)) << 4) | ((c4 & 1) << 3))] = u;
        }
    }
    __syncthreads();

    unsigned xs_base = (unsigned)__cvta_generic_to_shared(Xs);
    unsigned ws_base = (unsigned)__cvta_generic_to_shared(Ws);

    float acc[2][NFRAG][4];
#pragma unroll
    for (int mf = 0; mf < 2; mf++)
#pragma unroll
        for (int nf = 0; nf < NFRAG; nf++)
#pragma unroll
            for (int c = 0; c < 4; c++) acc[mf][nf][c] = 0.f;

#pragma unroll
    for (int ks = 0; ks < 8; ks++) {
        // A fragments (2 per warp: m16 each)
        unsigned a[2][4];
#pragma unroll
        for (int mf = 0; mf < 2; mf++) {
            int row = warp_m * 32 + mf * 16 + (l & 15);
            int colh = ks * 16 + (l >> 4) * 8;
            unsigned addr = xs_base + row * XROWB + ((((colh >> 3) ^ (row & 7))) << 4);
            LDSM_X4(a[mf][0], a[mf][1], a[mf][2], a[mf][3], addr);
        }
        // B fragments (NFRAG n8 frags; 2 per ldmatrix.x4.trans)
        unsigned b[NFRAG][2];
#pragma unroll
        for (int g2 = 0; g2 < NFRAG / 2; g2++) {
            int brow = ks * 16 + (l & 15);
            int bcol = warp_n * WN + g2 * 16 + (l >> 4) * 8;
            unsigned addr = ws_base + brow * WROWB + ((((bcol >> 3) ^ (brow & 7))) << 4);
            unsigned r0, r1, r2, r3;
            LDSM_X4_T(r0, r1, r2, r3, addr);
            b[2 * g2][0] = r0; b[2 * g2][1] = r1;
            b[2 * g2 + 1][0] = r2; b[2 * g2 + 1][1] = r3;
        }
#pragma unroll
        for (int mf = 0; mf < 2; mf++)
#pragma unroll
            for (int nf = 0; nf < NFRAG; nf++)
                MMA_16816(acc[mf][nf], a[mf], b[nf]);
    }

    // ---- epilogue: scale by dinv, fp16 stores ----
    int g = l >> 2;
    int c2 = (l & 3) * 2;
#pragma unroll
    for (int mf = 0; mf < 2; mf++) {
        int r_lo = row0 + warp_m * 32 + mf * 16 + g;
        int r_hi = r_lo + 8;
        float di_lo = (r_lo < N) ? dinv[r_lo] : 0.f;
        float di_hi = (r_hi < N) ? dinv[r_hi] : 0.f;
#pragma unroll
        for (int nf = 0; nf < NFRAG; nf++) {
            int col = warp_n * WN + nf * 8 + c2;
            if (r_lo < N) {
                __half2 h = __floats2half2_rn(di_lo * acc[mf][nf][0], di_lo * acc[mf][nf][1]);
                *(__half2*)&Yh[(size_t)r_lo * FO + col] = h;
            }
            if (r_hi < N) {
                __half2 h = __floats2half2_rn(di_hi * acc[mf][nf][2], di_hi * acc[mf][nf][3]);
                *(__half2*)&Yh[(size_t)r_hi * FO + col] = h;
            }
        }
    }
}

// ---------------- half helpers ----------------
__device__ __forceinline__ float4 h4_to_f4(uint2 u) {
    float2 fa = __half22float2(*(__half2*)&u.x);
    float2 fb = __half22float2(*(__half2*)&u.y);
    return make_float4(fa.x, fa.y, fb.x, fb.y);
}

// ---------------- fused pull-aggregation + relu: warp per node, 128 ch, fp16 out ----------------
__global__ void agg_relu128(const int* __restrict__ rowptr, const int* __restrict__ col,
                            const __half* __restrict__ Yh, const float* __restrict__ dinv,
                            const float* __restrict__ bias, __half* __restrict__ H, int N) {
    int node = (blockIdx.x * blockDim.x + threadIdx.x) >> 5;
    int lane = threadIdx.x & 31;
    if (node >= N) return;
    const uint2* Y2 = (const uint2*)Yh;
    float4 acc = h4_to_f4(Y2[(size_t)node * 32 + lane]);
    int j = rowptr[node];
    int end = rowptr[node + 1];
    for (; j + 4 <= end; j += 4) {
        int s0 = __ldg(&col[j]);
        int s1 = __ldg(&col[j + 1]);
        int s2 = __ldg(&col[j + 2]);
        int s3 = __ldg(&col[j + 3]);
        float4 v0 = h4_to_f4(Y2[(size_t)s0 * 32 + lane]);
        float4 v1 = h4_to_f4(Y2[(size_t)s1 * 32 + lane]);
        float4 v2 = h4_to_f4(Y2[(size_t)s2 * 32 + lane]);
        float4 v3 = h4_to_f4(Y2[(size_t)s3 * 32 + lane]);
        acc.x += v0.x + v1.x + v2.x + v3.x;
        acc.y += v0.y + v1.y + v2.y + v3.y;
        acc.z += v0.z + v1.z + v2.z + v3.z;
        acc.w += v0.w + v1.w + v2.w + v3.w;
    }
    for (; j < end; j++) {
        int s = __ldg(&col[j]);
        float4 v = h4_to_f4(Y2[(size_t)s * 32 + lane]);
        acc.x += v.x; acc.y += v.y; acc.z += v.z; acc.w += v.w;
    }
    float di = dinv[node];
    float4 b = ((const float4*)bias)[lane];
    __half2 p0 = __floats2half2_rn(fmaxf(fmaf(di, acc.x, b.x), 0.f),
                                   fmaxf(fmaf(di, acc.y, b.y), 0.f));
    __half2 p1 = __floats2half2_rn(fmaxf(fmaf(di, acc.z, b.z), 0.f),
                                   fmaxf(fmaf(di, acc.w, b.w), 0.f));
    uint2 u;
    u.x = *(unsigned*)&p0;
    u.y = *(unsigned*)&p1;
    ((uint2*)H)[(size_t)node * 32 + lane] = u;
}

// ---------------- fused pull-aggregation + log_softmax: warp per node, 64 ch ----------------
__global__ void agg_lsm64(const int* __restrict__ rowptr, const int* __restrict__ col,
                          const __half* __restrict__ Yh, const float* __restrict__ dinv,
                          const float* __restrict__ bias, float2* __restrict__ Out, int N) {
    int node = (blockIdx.x * blockDim.x + threadIdx.x) >> 5;
    int lane = threadIdx.x & 31;
    if (node >= N) return;
    const unsigned* Y1 = (const unsigned*)Yh;
    float2 acc;
    {
        unsigned u = Y1[(size_t)node * 32 + lane];
        acc = __half22float2(*(__half2*)&u);
    }
    int j = rowptr[node];
    int end = rowptr[node + 1];
    for (; j + 4 <= end; j += 4) {
        int s0 = __ldg(&col[j]);
        int s1 = __ldg(&col[j + 1]);
        int s2 = __ldg(&col[j + 2]);
        int s3 = __ldg(&col[j + 3]);
        unsigned u0 = Y1[(size_t)s0 * 32 + lane];
        unsigned u1 = Y1[(size_t)s1 * 32 + lane];
        unsigned u2 = Y1[(size_t)s2 * 32 + lane];
        unsigned u3 = Y1[(size_t)s3 * 32 + lane];
        float2 v0 = __half22float2(*(__half2*)&u0);
        float2 v1 = __half22float2(*(__half2*)&u1);
        float2 v2 = __half22float2(*(__half2*)&u2);
        float2 v3 = __half22float2(*(__half2*)&u3);
        acc.x += v0.x + v1.x + v2.x + v3.x;
        acc.y += v0.y + v1.y + v2.y + v3.y;
    }
    for (; j < end; j++) {
        int s = __ldg(&col[j]);
        unsigned u = Y1[(size_t)s * 32 + lane];
        float2 v = __half22float2(*(__half2*)&u);
        acc.x += v.x; acc.y += v.y;
    }
    float di = dinv[node];
    float2 b = ((const float2*)bias)[lane];
    float vx = fmaf(di, acc.x, b.x);
    float vy = fmaf(di, acc.y, b.y);
    float m = fmaxf(vx, vy);
#pragma unroll
    for (int o = 16; o > 0; o >>= 1)
        m = fmaxf(m, __shfl_xor_sync(0xFFFFFFFFu, m, o));
    float s = expf(vx - m) + expf(vy - m);
#pragma unroll
    for (int o = 16; o > 0; o >>= 1)
        s += __shfl_xor_sync(0xFFFFFFFFu, s, o);
    float ls = m + logf(s);
    float2 o2;
    o2.x = vx - ls;
    o2.y = vy - ls;
    Out[(size_t)node * 32 + lane] = o2;
}

// ---------------- driver ----------------
extern "C" void kernel_launch(void* const* d_in, const int* in_sizes, int n_in,
                              void* d_out, int out_size) {
    const float* x   = (const float*)d_in[0];
    const int*   ei  = (const int*)d_in[1];
    const float* W1  = (const float*)d_in[2];
    const float* b1  = (const float*)d_in[3];
    const float* W2  = (const float*)d_in[4];
    const float* b2  = (const float*)d_in[5];
    const float* W3  = (const float*)d_in[6];
    const float* b3  = (const float*)d_in[7];
    float* out = (float*)d_out;

    int N = in_sizes[0] / 128;
    int E = in_sizes[1] / 2;
    const int* src = ei;
    const int* dst = ei + E;

    __half *xh, *yh, *h;
    float* dinv;
    int *cnt, *excl, *bsum, *rowptr, *cursor, *col;
    cudaGetSymbolAddress((void**)&xh, g_xh);
    cudaGetSymbolAddress((void**)&yh, g_yh);
    cudaGetSymbolAddress((void**)&h, g_h);
    cudaGetSymbolAddress((void**)&dinv, g_dinv);
    cudaGetSymbolAddress((void**)&cnt, g_cnt);
    cudaGetSymbolAddress((void**)&excl, g_excl);
    cudaGetSymbolAddress((void**)&bsum, g_bsum);
    cudaGetSymbolAddress((void**)&rowptr, g_rowptr);
    cudaGetSymbolAddress((void**)&cursor, g_cursor);
    cudaGetSymbolAddress((void**)&col, g_col);

    constexpr int SMEM128 = 128 * 256 + 128 * 256;  // 65536
    constexpr int SMEM64  = 128 * 256 + 128 * 128;  // 49152
    cudaFuncSetAttribute(gemm_hmma<128>, cudaFuncAttributeMaxDynamicSharedMemorySize, SMEM128);
    cudaFuncSetAttribute(gemm_hmma<64>,  cudaFuncAttributeMaxDynamicSharedMemorySize, SMEM64);

    int nb_nodes = (N + 255) / 256;
    int nb_edges = (E + 255) / 256;
    int nb_scan  = (N + 1023) / 1024;

    // ---- prep: degree, dinv, CSR, x->fp16 ----
    zero_cnt<<<nb_nodes, 256>>>(cnt, N);
    count_deg<<<nb_edges, 256>>>(dst, cnt, E, N);
    calc_dinv<<<nb_nodes, 256>>>(cnt, dinv, N);
    scan_block<<<nb_scan, 1024>>>(cnt, excl, bsum, N);
    scan_partials<<<1, 128>>>(bsum, nb_scan);
    scan_finish<<<(N + 256) / 256, 256>>>(excl, bsum, rowptr, cursor, N, E);
    fill_csr<<<nb_edges, 256>>>(src, dst, cursor, col, E, N);
    conv_x<<<(N * 32 + 255) / 256, 256>>>((const float4*)x, (uint2*)xh, N * 32);

    int gemm_blocks = (N + 127) / 128;
    int agg_blocks  = ((size_t)N * 32 + 255) / 256;

    // ---- layer 1 ----
    gemm_hmma<128><<<gemm_blocks, 256, SMEM128>>>(xh, W1, dinv, yh, N);
    agg_relu128<<<agg_blocks, 256>>>(rowptr, col, yh, dinv, b1, h, N);
    // ---- layer 2 ----
    gemm_hmma<128><<<gemm_blocks, 256, SMEM128>>>(h, W2, dinv, yh, N);
    agg_relu128<<<agg_blocks, 256>>>(rowptr, col, yh, dinv, b2, h, N);
    // ---- layer 3 ----
    gemm_hmma<64><<<gemm_blocks, 256, SMEM64>>>(h, W3, dinv, yh, N);
    agg_lsm64<<<agg_blocks, 256>>>(rowptr, col, yh, dinv, b3, (float2*)out, N);
}